// round 1
// baseline (speedup 1.0000x reference)
#include <cuda_runtime.h>

#define NN 50000
#define EE 1600000
#define HD 128
#define GG 512
#define OUTD 10
#define KSTEPS 10
#define ALPHA 0.1f

// Scratch (device globals; no dynamic allocation allowed)
__device__ float g_h [NN * HD];   // teleport term h = x0
__device__ float g_xa[NN * HD];   // ping
__device__ float g_xb[NN * HD];   // pong
__device__ float g_Wc[HD * HD];   // fused W1@W2
__device__ float g_bc[HD];        // fused b1@W2 + b2
__device__ float g_pooled[GG * HD];

__device__ __forceinline__ float* buf_sel(int w) {
    return (w == 0) ? g_h : ((w == 1) ? g_xa : g_xb);
}

// ---------------------------------------------------------------------------
// Fuse the two stacked linears: Wc = W1 @ W2, bc = b1 @ W2 + b2
// grid = 16 blocks x 128 threads; block b handles d in [8b, 8b+8)
// ---------------------------------------------------------------------------
__global__ void k_wc(const float* __restrict__ W1, const float* __restrict__ b1,
                     const float* __restrict__ W2, const float* __restrict__ b2) {
    int h = threadIdx.x;
    int d0 = blockIdx.x * 8;
    for (int d = d0; d < d0 + 8; ++d) {
        float s = 0.f;
        #pragma unroll 8
        for (int k = 0; k < HD; ++k) s += W1[d * HD + k] * W2[k * HD + h];
        g_Wc[d * HD + h] = s;
    }
    if (blockIdx.x == 0) {
        float s = b2[h];
        #pragma unroll 8
        for (int k = 0; k < HD; ++k) s += b1[k] * W2[k * HD + h];
        g_bc[h] = s;
    }
}

// ---------------------------------------------------------------------------
// x0 = F^T @ Wc + bc   (F is [128, N] in_dim-major)
// Tile: 64 nodes x 128 cols per block, 256 threads, 4x8 register tile each.
// ---------------------------------------------------------------------------
__global__ __launch_bounds__(256) void k_x0(const float* __restrict__ F) {
    __shared__ float Fs[32][64];    // d-chunk x nodes
    __shared__ float Ws[32][128];   // d-chunk x cols
    int t  = threadIdx.x;
    int nb = blockIdx.x * 64;
    int n0 = (t & 15) * 4;          // node offset in tile
    int h0 = (t >> 4) * 8;          // col  offset in tile

    float acc[4][8];
    #pragma unroll
    for (int i = 0; i < 4; ++i)
        #pragma unroll
        for (int j = 0; j < 8; ++j) acc[i][j] = 0.f;

    for (int c = 0; c < 4; ++c) {
        __syncthreads();
        for (int i = t; i < 32 * 64; i += 256) {
            int dd = i >> 6, nn = i & 63, n = nb + nn;
            Fs[dd][nn] = (n < NN) ? F[(c * 32 + dd) * NN + n] : 0.f;
        }
        for (int i = t; i < 32 * 128; i += 256) {
            int dd = i >> 7, hh = i & 127;
            Ws[dd][hh] = g_Wc[(c * 32 + dd) * HD + hh];
        }
        __syncthreads();
        #pragma unroll
        for (int d = 0; d < 32; ++d) {
            float4 fa = *(const float4*)&Fs[d][n0];
            float4 w0 = *(const float4*)&Ws[d][h0];
            float4 w1 = *(const float4*)&Ws[d][h0 + 4];
            float f[4] = {fa.x, fa.y, fa.z, fa.w};
            float w[8] = {w0.x, w0.y, w0.z, w0.w, w1.x, w1.y, w1.z, w1.w};
            #pragma unroll
            for (int i = 0; i < 4; ++i)
                #pragma unroll
                for (int j = 0; j < 8; ++j) acc[i][j] += f[i] * w[j];
        }
    }
    #pragma unroll
    for (int i = 0; i < 4; ++i) {
        int n = nb + n0 + i;
        if (n < NN) {
            #pragma unroll
            for (int j = 0; j < 8; j += 4) {
                float4 o = make_float4(acc[i][j]     + g_bc[h0 + j],
                                       acc[i][j + 1] + g_bc[h0 + j + 1],
                                       acc[i][j + 2] + g_bc[h0 + j + 2],
                                       acc[i][j + 3] + g_bc[h0 + j + 3]);
                *(float4*)&g_h[n * HD + h0 + j] = o;
            }
        }
    }
}

// ---------------------------------------------------------------------------
// x_next = ALPHA * h   (elementwise init before the edge scatter)
// ---------------------------------------------------------------------------
__global__ void k_init(int outw) {
    float* out = buf_sel(outw);
    int i = blockIdx.x * 256 + threadIdx.x;           // NN*HD/4 = 1.6M exact
    float4 v = ((const float4*)g_h)[i];
    ((float4*)out)[i] = make_float4(ALPHA * v.x, ALPHA * v.y,
                                    ALPHA * v.z, ALPHA * v.w);
}

// ---------------------------------------------------------------------------
// Edge scatter: x_next[dst] += 0.9 * w_e * x_cur[src]
// One warp per edge; each lane handles one float4 (128 cols / 32 lanes).
// Vector atomics (RED.128) keep us near the L2 throughput ceiling.
// ---------------------------------------------------------------------------
__global__ __launch_bounds__(256) void k_edge(int inw, int outw,
                                              const int*   __restrict__ ei,
                                              const float* __restrict__ ew) {
    const float* xin  = buf_sel(inw);
    float*       xout = buf_sel(outw);
    unsigned tid = blockIdx.x * 256u + threadIdx.x;
    unsigned e = tid >> 5;
    if (e >= EE) return;
    int lane = tid & 31;
    int src = __ldg(&ei[e]);
    int dst = __ldg(&ei[EE + e]);
    float w = 0.9f * __ldg(&ew[e]);
    float4 v = *(const float4*)&xin[src * HD + lane * 4];
    atomicAdd((float4*)&xout[dst * HD + lane * 4],
              make_float4(w * v.x, w * v.y, w * v.z, w * v.w));
}

// ---------------------------------------------------------------------------
// Pooling: pooled[batch[n]] += x_final[n]
// ---------------------------------------------------------------------------
__global__ void k_zero_pool() {
    int i = blockIdx.x * 256 + threadIdx.x;           // GG*HD = 65536 exact
    g_pooled[i] = 0.f;
}

__global__ __launch_bounds__(256) void k_pool(const int* __restrict__ batch) {
    unsigned tid = blockIdx.x * 256u + threadIdx.x;
    unsigned n = tid >> 5;
    if (n >= NN) return;
    int lane = tid & 31;
    int g = __ldg(&batch[n]);
    float4 v = *(const float4*)&g_xb[n * HD + lane * 4];  // K=10 -> final in g_xb
    atomicAdd((float4*)&g_pooled[g * HD + lane * 4], v);
}

// ---------------------------------------------------------------------------
// Head: relu(pooled @ V0w + V0b) @ V1w + V1b -> log_softmax
// One block (128 threads) per graph.
// ---------------------------------------------------------------------------
__global__ __launch_bounds__(128) void k_head(const float* __restrict__ V0w,
                                              const float* __restrict__ V0b,
                                              const float* __restrict__ V1w,
                                              const float* __restrict__ V1b,
                                              float* __restrict__ out) {
    int g = blockIdx.x, t = threadIdx.x;
    __shared__ float p[HD];
    __shared__ float hid[HD];
    __shared__ float y[OUTD];
    p[t] = g_pooled[g * HD + t];
    __syncthreads();
    float a = V0b[t];
    #pragma unroll 8
    for (int d = 0; d < HD; ++d) a += p[d] * V0w[d * HD + t];
    hid[t] = fmaxf(a, 0.f);
    __syncthreads();
    if (t < OUTD) {
        float s = V1b[t];
        #pragma unroll 8
        for (int hh = 0; hh < HD; ++hh) s += hid[hh] * V1w[hh * OUTD + t];
        y[t] = s;
    }
    __syncthreads();
    if (t < OUTD) {
        float m = y[0];
        #pragma unroll
        for (int o = 1; o < OUTD; ++o) m = fmaxf(m, y[o]);
        float s = 0.f;
        #pragma unroll
        for (int o = 0; o < OUTD; ++o) s += expf(y[o] - m);
        out[g * OUTD + t] = y[t] - m - logf(s);
    }
}

// ---------------------------------------------------------------------------
extern "C" void kernel_launch(void* const* d_in, const int* in_sizes, int n_in,
                              void* d_out, int out_size) {
    const float* features    = (const float*)d_in[0];
    const float* edge_weight = (const float*)d_in[1];
    const float* W1          = (const float*)d_in[2];
    const float* b1          = (const float*)d_in[3];
    const float* W2          = (const float*)d_in[4];
    const float* b2          = (const float*)d_in[5];
    const float* V0w         = (const float*)d_in[6];
    const float* V0b         = (const float*)d_in[7];
    const float* V1w         = (const float*)d_in[8];
    const float* V1b         = (const float*)d_in[9];
    const int*   edge_index  = (const int*)d_in[10];
    const int*   batch       = (const int*)d_in[11];
    float*       out         = (float*)d_out;

    k_wc<<<16, 128>>>(W1, b1, W2, b2);
    k_x0<<<(NN + 63) / 64, 256>>>(features);

    const int init_grid = (NN * HD / 4) / 256;        // 6250
    const int edge_grid = (EE * 32) / 256;            // 200000
    for (int k = 0; k < KSTEPS; ++k) {
        int outw = (k % 2 == 0) ? 1 : 2;              // g_xa / g_xb
        int inw  = (k == 0) ? 0 : ((k % 2 == 0) ? 2 : 1);
        k_init<<<init_grid, 256>>>(outw);
        k_edge<<<edge_grid, 256>>>(inw, outw, edge_index, edge_weight);
    }

    k_zero_pool<<<(GG * HD) / 256, 256>>>();
    k_pool<<<(NN * 32 + 255) / 256, 256>>>(batch);
    k_head<<<GG, 128>>>(V0w, V0b, V1w, V1b, out);
}

// round 2
// speedup vs baseline: 2.5381x; 2.5381x over previous
#include <cuda_runtime.h>

#define NN 50000
#define EE 1600000
#define HD 128
#define GG 512
#define OUTD 10
#define KSTEPS 10
#define ALPHA 0.1f

// Scratch (device globals; no dynamic allocation allowed)
__device__ float g_h [NN * HD];   // teleport term h = x0
__device__ float g_xa[NN * HD];   // ping
__device__ float g_xb[NN * HD];   // pong
__device__ float g_Wc[HD * HD];   // fused W1@W2
__device__ float g_bc[HD];        // fused b1@W2 + b2
__device__ float g_pooled[GG * HD];

// CSR (dst-sorted) built per launch
__device__ int   g_deg[NN];
__device__ int   g_cursor[NN];
__device__ int   g_rowptr[NN + 1];
__device__ int   g_src[EE];
__device__ float g_w[EE];

// ---------------------------------------------------------------------------
// Fuse the two stacked linears: Wc = W1 @ W2, bc = b1 @ W2 + b2
// ---------------------------------------------------------------------------
__global__ void k_wc(const float* __restrict__ W1, const float* __restrict__ b1,
                     const float* __restrict__ W2, const float* __restrict__ b2) {
    int h = threadIdx.x;
    int d0 = blockIdx.x * 8;
    for (int d = d0; d < d0 + 8; ++d) {
        float s = 0.f;
        #pragma unroll 8
        for (int k = 0; k < HD; ++k) s += W1[d * HD + k] * W2[k * HD + h];
        g_Wc[d * HD + h] = s;
    }
    if (blockIdx.x == 0) {
        float s = b2[h];
        #pragma unroll 8
        for (int k = 0; k < HD; ++k) s += b1[k] * W2[k * HD + h];
        g_bc[h] = s;
    }
}

// ---------------------------------------------------------------------------
// x0 = F^T @ Wc + bc   (F is [128, N] in_dim-major)
// ---------------------------------------------------------------------------
__global__ __launch_bounds__(256) void k_x0(const float* __restrict__ F) {
    __shared__ float Fs[32][64];
    __shared__ float Ws[32][128];
    int t  = threadIdx.x;
    int nb = blockIdx.x * 64;
    int n0 = (t & 15) * 4;
    int h0 = (t >> 4) * 8;

    float acc[4][8];
    #pragma unroll
    for (int i = 0; i < 4; ++i)
        #pragma unroll
        for (int j = 0; j < 8; ++j) acc[i][j] = 0.f;

    for (int c = 0; c < 4; ++c) {
        __syncthreads();
        for (int i = t; i < 32 * 64; i += 256) {
            int dd = i >> 6, nn = i & 63, n = nb + nn;
            Fs[dd][nn] = (n < NN) ? F[(c * 32 + dd) * NN + n] : 0.f;
        }
        for (int i = t; i < 32 * 128; i += 256) {
            int dd = i >> 7, hh = i & 127;
            Ws[dd][hh] = g_Wc[(c * 32 + dd) * HD + hh];
        }
        __syncthreads();
        #pragma unroll
        for (int d = 0; d < 32; ++d) {
            float4 fa = *(const float4*)&Fs[d][n0];
            float4 w0 = *(const float4*)&Ws[d][h0];
            float4 w1 = *(const float4*)&Ws[d][h0 + 4];
            float f[4] = {fa.x, fa.y, fa.z, fa.w};
            float w[8] = {w0.x, w0.y, w0.z, w0.w, w1.x, w1.y, w1.z, w1.w};
            #pragma unroll
            for (int i = 0; i < 4; ++i)
                #pragma unroll
                for (int j = 0; j < 8; ++j) acc[i][j] += f[i] * w[j];
        }
    }
    #pragma unroll
    for (int i = 0; i < 4; ++i) {
        int n = nb + n0 + i;
        if (n < NN) {
            #pragma unroll
            for (int j = 0; j < 8; j += 4) {
                float4 o = make_float4(acc[i][j]     + g_bc[h0 + j],
                                       acc[i][j + 1] + g_bc[h0 + j + 1],
                                       acc[i][j + 2] + g_bc[h0 + j + 2],
                                       acc[i][j + 3] + g_bc[h0 + j + 3]);
                *(float4*)&g_h[n * HD + h0 + j] = o;
            }
        }
    }
}

// ---------------------------------------------------------------------------
// CSR construction: histogram -> exclusive scan -> scatter
// ---------------------------------------------------------------------------
__global__ void k_zero_deg() {
    int i = blockIdx.x * 256 + threadIdx.x;
    if (i < NN) g_deg[i] = 0;
}

__global__ __launch_bounds__(256) void k_hist(const int* __restrict__ ei) {
    int e = blockIdx.x * 256 + threadIdx.x;
    if (e < EE) atomicAdd(&g_deg[ei[EE + e]], 1);
}

// Single-block exclusive scan of g_deg -> g_rowptr (+ init g_cursor)
__global__ __launch_bounds__(1024) void k_scan() {
    __shared__ int sums[1024];
    int t = threadIdx.x;
    const int CH = (NN + 1023) / 1024;   // 49
    int start = t * CH;
    int s = 0;
    for (int i = 0; i < CH; ++i) {
        int idx = start + i;
        if (idx < NN) s += g_deg[idx];
    }
    sums[t] = s;
    __syncthreads();
    for (int off = 1; off < 1024; off <<= 1) {
        int v = 0;
        if (t >= off) v = sums[t - off];
        __syncthreads();
        if (t >= off) sums[t] += v;
        __syncthreads();
    }
    int run = sums[t] - s;   // exclusive prefix of this chunk
    for (int i = 0; i < CH; ++i) {
        int idx = start + i;
        if (idx < NN) {
            g_rowptr[idx] = run;
            g_cursor[idx] = run;
            run += g_deg[idx];
        }
    }
    if (t == 1023) g_rowptr[NN] = EE;
}

__global__ __launch_bounds__(256) void k_scatter(const int*   __restrict__ ei,
                                                 const float* __restrict__ ew) {
    int e = blockIdx.x * 256 + threadIdx.x;
    if (e >= EE) return;
    int dst = ei[EE + e];
    int pos = atomicAdd(&g_cursor[dst], 1);
    g_src[pos] = ei[e];
    g_w[pos]   = 0.9f * ew[e];
}

// ---------------------------------------------------------------------------
// Propagation, atomic-free: one warp per dst node, lane owns 4 columns.
// xout[n] = sum_e 0.9*w_e*xin[src_e] + ALPHA*h[n]
// ---------------------------------------------------------------------------
__global__ __launch_bounds__(256) void k_prop(const float* __restrict__ xin,
                                              float* __restrict__ xout) {
    unsigned warp = (blockIdx.x * 256u + threadIdx.x) >> 5;
    if (warp >= NN) return;
    int lane = threadIdx.x & 31;
    int beg = g_rowptr[warp];
    int end = g_rowptr[warp + 1];

    float4 acc = make_float4(0.f, 0.f, 0.f, 0.f);
    for (int j0 = beg; j0 < end; j0 += 32) {
        int cnt = end - j0;
        if (cnt > 32) cnt = 32;
        int   s = 0;
        float w = 0.f;
        if (lane < cnt) { s = g_src[j0 + lane] * HD; w = g_w[j0 + lane]; }
        #pragma unroll 4
        for (int t = 0; t < cnt; ++t) {
            int   ss = __shfl_sync(0xffffffffu, s, t);
            float ww = __shfl_sync(0xffffffffu, w, t);
            float4 v = *(const float4*)&xin[ss + lane * 4];
            acc.x += ww * v.x;
            acc.y += ww * v.y;
            acc.z += ww * v.z;
            acc.w += ww * v.w;
        }
    }
    float4 hv = *(const float4*)&g_h[warp * HD + lane * 4];
    *(float4*)&xout[warp * HD + lane * 4] =
        make_float4(acc.x + ALPHA * hv.x, acc.y + ALPHA * hv.y,
                    acc.z + ALPHA * hv.z, acc.w + ALPHA * hv.w);
}

// ---------------------------------------------------------------------------
// Pooling + head
// ---------------------------------------------------------------------------
__global__ void k_zero_pool() {
    int i = blockIdx.x * 256 + threadIdx.x;
    g_pooled[i] = 0.f;
}

__global__ __launch_bounds__(256) void k_pool(const int* __restrict__ batch) {
    unsigned tid = blockIdx.x * 256u + threadIdx.x;
    unsigned n = tid >> 5;
    if (n >= NN) return;
    int lane = tid & 31;
    int g = __ldg(&batch[n]);
    float4 v = *(const float4*)&g_xb[n * HD + lane * 4];
    atomicAdd((float4*)&g_pooled[g * HD + lane * 4], v);
}

__global__ __launch_bounds__(128) void k_head(const float* __restrict__ V0w,
                                              const float* __restrict__ V0b,
                                              const float* __restrict__ V1w,
                                              const float* __restrict__ V1b,
                                              float* __restrict__ out) {
    int g = blockIdx.x, t = threadIdx.x;
    __shared__ float p[HD];
    __shared__ float hid[HD];
    __shared__ float y[OUTD];
    p[t] = g_pooled[g * HD + t];
    __syncthreads();
    float a = V0b[t];
    #pragma unroll 8
    for (int d = 0; d < HD; ++d) a += p[d] * V0w[d * HD + t];
    hid[t] = fmaxf(a, 0.f);
    __syncthreads();
    if (t < OUTD) {
        float s = V1b[t];
        #pragma unroll 8
        for (int hh = 0; hh < HD; ++hh) s += hid[hh] * V1w[hh * OUTD + t];
        y[t] = s;
    }
    __syncthreads();
    if (t < OUTD) {
        float m = y[0];
        #pragma unroll
        for (int o = 1; o < OUTD; ++o) m = fmaxf(m, y[o]);
        float s = 0.f;
        #pragma unroll
        for (int o = 0; o < OUTD; ++o) s += expf(y[o] - m);
        out[g * OUTD + t] = y[t] - m - logf(s);
    }
}

// ---------------------------------------------------------------------------
extern "C" void kernel_launch(void* const* d_in, const int* in_sizes, int n_in,
                              void* d_out, int out_size) {
    const float* features    = (const float*)d_in[0];
    const float* edge_weight = (const float*)d_in[1];
    const float* W1          = (const float*)d_in[2];
    const float* b1          = (const float*)d_in[3];
    const float* W2          = (const float*)d_in[4];
    const float* b2          = (const float*)d_in[5];
    const float* V0w         = (const float*)d_in[6];
    const float* V0b         = (const float*)d_in[7];
    const float* V1w         = (const float*)d_in[8];
    const float* V1b         = (const float*)d_in[9];
    const int*   edge_index  = (const int*)d_in[10];
    const int*   batch       = (const int*)d_in[11];
    float*       out         = (float*)d_out;

    // CSR build (overlappable with the dense front-end on different SMs)
    k_zero_deg<<<(NN + 255) / 256, 256>>>();
    k_hist<<<(EE + 255) / 256, 256>>>(edge_index);
    k_scan<<<1, 1024>>>();
    k_scatter<<<(EE + 255) / 256, 256>>>(edge_index, edge_weight);

    // Dense front-end
    k_wc<<<16, 128>>>(W1, b1, W2, b2);
    k_x0<<<(NN + 63) / 64, 256>>>(features);

    // APPNP propagation, atomic-free
    float* xa = nullptr; float* xb = nullptr; float* xh = nullptr;
    cudaGetSymbolAddress((void**)&xa, g_xa);
    cudaGetSymbolAddress((void**)&xb, g_xb);
    cudaGetSymbolAddress((void**)&xh, g_h);

    const int prop_grid = (NN * 32 + 255) / 256;   // 6250
    const float* cur = xh;
    for (int k = 0; k < KSTEPS; ++k) {
        float* nxt = (k % 2 == 0) ? xa : xb;
        k_prop<<<prop_grid, 256>>>(cur, nxt);
        cur = nxt;
    }

    // Pooling + head (final x lives in g_xb after 10 steps)
    k_zero_pool<<<(GG * HD) / 256, 256>>>();
    k_pool<<<(NN * 32 + 255) / 256, 256>>>(batch);
    k_head<<<GG, 128>>>(V0w, V0b, V1w, V1b, out);
}

// round 3
// speedup vs baseline: 2.9039x; 1.1441x over previous
#include <cuda_runtime.h>

#define NN 50000
#define EE 1600000
#define HD 128
#define GG 512
#define OUTD 10
#define KSTEPS 10
#define ALPHA 0.1f
#define NB 196            // ceil(NN/256)

// Scratch (device globals; no dynamic allocation allowed)
__device__ float g_h [NN * HD];   // teleport term h = x0
__device__ float g_xa[NN * HD];   // ping
__device__ float g_xb[NN * HD];   // pong
__device__ float g_Wc[HD * HD];   // fused W1@W2
__device__ float g_bc[HD];        // fused b1@W2 + b2
__device__ float g_pooled[GG * HD];

// CSR (dst-sorted) built per launch
__device__ int  g_deg[NN];
__device__ int  g_cursor[NN];
__device__ int  g_rowptr[NN + 1];
__device__ int  g_bsum[NB];
__device__ int  g_boff[NB];
__device__ int2 g_sw[EE];         // packed (src, weight-bits)

// ---------------------------------------------------------------------------
// Fuse the two stacked linears: Wc = W1 @ W2, bc = b1 @ W2 + b2
// ---------------------------------------------------------------------------
__global__ void k_wc(const float* __restrict__ W1, const float* __restrict__ b1,
                     const float* __restrict__ W2, const float* __restrict__ b2) {
    int h = threadIdx.x;
    int d0 = blockIdx.x * 8;
    for (int d = d0; d < d0 + 8; ++d) {
        float s = 0.f;
        #pragma unroll 8
        for (int k = 0; k < HD; ++k) s += W1[d * HD + k] * W2[k * HD + h];
        g_Wc[d * HD + h] = s;
    }
    if (blockIdx.x == 0) {
        float s = b2[h];
        #pragma unroll 8
        for (int k = 0; k < HD; ++k) s += b1[k] * W2[k * HD + h];
        g_bc[h] = s;
    }
}

// ---------------------------------------------------------------------------
// x0 = F^T @ Wc + bc   (F is [128, N] in_dim-major)
// ---------------------------------------------------------------------------
__global__ __launch_bounds__(256) void k_x0(const float* __restrict__ F) {
    __shared__ float Fs[32][64];
    __shared__ float Ws[32][128];
    int t  = threadIdx.x;
    int nb = blockIdx.x * 64;
    int n0 = (t & 15) * 4;
    int h0 = (t >> 4) * 8;

    float acc[4][8];
    #pragma unroll
    for (int i = 0; i < 4; ++i)
        #pragma unroll
        for (int j = 0; j < 8; ++j) acc[i][j] = 0.f;

    for (int c = 0; c < 4; ++c) {
        __syncthreads();
        for (int i = t; i < 32 * 64; i += 256) {
            int dd = i >> 6, nn = i & 63, n = nb + nn;
            Fs[dd][nn] = (n < NN) ? F[(c * 32 + dd) * NN + n] : 0.f;
        }
        for (int i = t; i < 32 * 128; i += 256) {
            int dd = i >> 7, hh = i & 127;
            Ws[dd][hh] = g_Wc[(c * 32 + dd) * HD + hh];
        }
        __syncthreads();
        #pragma unroll
        for (int d = 0; d < 32; ++d) {
            float4 fa = *(const float4*)&Fs[d][n0];
            float4 w0 = *(const float4*)&Ws[d][h0];
            float4 w1 = *(const float4*)&Ws[d][h0 + 4];
            float f[4] = {fa.x, fa.y, fa.z, fa.w};
            float w[8] = {w0.x, w0.y, w0.z, w0.w, w1.x, w1.y, w1.z, w1.w};
            #pragma unroll
            for (int i = 0; i < 4; ++i)
                #pragma unroll
                for (int j = 0; j < 8; ++j) acc[i][j] += f[i] * w[j];
        }
    }
    #pragma unroll
    for (int i = 0; i < 4; ++i) {
        int n = nb + n0 + i;
        if (n < NN) {
            #pragma unroll
            for (int j = 0; j < 8; j += 4) {
                float4 o = make_float4(acc[i][j]     + g_bc[h0 + j],
                                       acc[i][j + 1] + g_bc[h0 + j + 1],
                                       acc[i][j + 2] + g_bc[h0 + j + 2],
                                       acc[i][j + 3] + g_bc[h0 + j + 3]);
                *(float4*)&g_h[n * HD + h0 + j] = o;
            }
        }
    }
}

// ---------------------------------------------------------------------------
// CSR construction: histogram -> (blocksum, scan, rowptr) -> scatter
// ---------------------------------------------------------------------------
__global__ void k_zero_deg() {
    int i = blockIdx.x * 256 + threadIdx.x;
    if (i < NN) g_deg[i] = 0;
}

__global__ __launch_bounds__(256) void k_hist(const int* __restrict__ ei) {
    int e = blockIdx.x * 256 + threadIdx.x;
    if (e < EE) atomicAdd(&g_deg[ei[EE + e]], 1);
}

__global__ __launch_bounds__(256) void k_blocksum() {
    __shared__ int sm[256];
    int t = threadIdx.x;
    int i = blockIdx.x * 256 + t;
    sm[t] = (i < NN) ? g_deg[i] : 0;
    __syncthreads();
    for (int off = 128; off > 0; off >>= 1) {
        if (t < off) sm[t] += sm[t + off];
        __syncthreads();
    }
    if (t == 0) g_bsum[blockIdx.x] = sm[0];
}

__global__ __launch_bounds__(256) void k_scan_bsum() {
    __shared__ int sm[256];
    int t = threadIdx.x;
    int v = (t < NB) ? g_bsum[t] : 0;
    sm[t] = v;
    __syncthreads();
    for (int off = 1; off < 256; off <<= 1) {
        int u = (t >= off) ? sm[t - off] : 0;
        __syncthreads();
        sm[t] += u;
        __syncthreads();
    }
    if (t < NB) g_boff[t] = sm[t] - v;   // exclusive
}

// blocks [0, NB): rowptr + cursor; blocks [NB, NB+256): zero g_pooled
__global__ __launch_bounds__(256) void k_rowptr_zeropool() {
    int t = threadIdx.x;
    int b = blockIdx.x;
    if (b >= NB) {
        int i = (b - NB) * 256 + t;      // GG*HD = 65536 = 256*256 exact
        g_pooled[i] = 0.f;
        return;
    }
    __shared__ int sm[256];
    int i = b * 256 + t;
    int v = (i < NN) ? g_deg[i] : 0;
    sm[t] = v;
    __syncthreads();
    for (int off = 1; off < 256; off <<= 1) {
        int u = (t >= off) ? sm[t - off] : 0;
        __syncthreads();
        sm[t] += u;
        __syncthreads();
    }
    int rp = g_boff[b] + sm[t] - v;      // exclusive prefix
    if (i < NN) { g_rowptr[i] = rp; g_cursor[i] = rp; }
    if (b == 0 && t == 0) g_rowptr[NN] = EE;
}

__global__ __launch_bounds__(256) void k_scatter(const int*   __restrict__ ei,
                                                 const float* __restrict__ ew) {
    int e = blockIdx.x * 256 + threadIdx.x;
    if (e >= EE) return;
    int dst = __ldg(&ei[EE + e]);
    int pos = atomicAdd(&g_cursor[dst], 1);
    g_sw[pos] = make_int2(__ldg(&ei[e]), __float_as_int(0.9f * __ldg(&ew[e])));
}

// ---------------------------------------------------------------------------
// Propagation, atomic-free: one warp per dst node, lane owns 4 columns.
// xout[n] = sum_e 0.9*w_e*xin[src_e] + ALPHA*h[n]
// final==1: atomically accumulate the row into g_pooled[batch[n]] instead.
// ---------------------------------------------------------------------------
__global__ __launch_bounds__(256) void k_prop(const float* __restrict__ xin,
                                              float* __restrict__ xout,
                                              int final_step,
                                              const int* __restrict__ batch) {
    unsigned warp = (blockIdx.x * 256u + threadIdx.x) >> 5;
    if (warp >= NN) return;
    int lane = threadIdx.x & 31;
    int beg = g_rowptr[warp];
    int end = g_rowptr[warp + 1];

    float4 acc = make_float4(0.f, 0.f, 0.f, 0.f);
    for (int j0 = beg; j0 < end; j0 += 32) {
        int cnt = end - j0;
        if (cnt > 32) cnt = 32;
        int   s = 0;
        float w = 0.f;
        if (lane < cnt) {
            int2 sw = __ldg(&g_sw[j0 + lane]);
            s = sw.x * HD;
            w = __int_as_float(sw.y);
        }
        #pragma unroll 4
        for (int t = 0; t < cnt; ++t) {
            int   ss = __shfl_sync(0xffffffffu, s, t);
            float ww = __shfl_sync(0xffffffffu, w, t);
            float4 v = *(const float4*)&xin[ss + lane * 4];
            acc.x += ww * v.x;
            acc.y += ww * v.y;
            acc.z += ww * v.z;
            acc.w += ww * v.w;
        }
    }
    float4 hv = *(const float4*)&g_h[warp * HD + lane * 4];
    float4 o = make_float4(acc.x + ALPHA * hv.x, acc.y + ALPHA * hv.y,
                           acc.z + ALPHA * hv.z, acc.w + ALPHA * hv.w);
    if (final_step) {
        int g = __ldg(&batch[warp]);
        atomicAdd((float4*)&g_pooled[g * HD + lane * 4], o);
    } else {
        *(float4*)&xout[warp * HD + lane * 4] = o;
    }
}

// ---------------------------------------------------------------------------
// Head: relu(pooled @ V0w + V0b) @ V1w + V1b -> log_softmax
// ---------------------------------------------------------------------------
__global__ __launch_bounds__(128) void k_head(const float* __restrict__ V0w,
                                              const float* __restrict__ V0b,
                                              const float* __restrict__ V1w,
                                              const float* __restrict__ V1b,
                                              float* __restrict__ out) {
    int g = blockIdx.x, t = threadIdx.x;
    __shared__ float p[HD];
    __shared__ float hid[HD];
    __shared__ float y[OUTD];
    p[t] = g_pooled[g * HD + t];
    __syncthreads();
    float a = V0b[t];
    #pragma unroll 8
    for (int d = 0; d < HD; ++d) a += p[d] * V0w[d * HD + t];
    hid[t] = fmaxf(a, 0.f);
    __syncthreads();
    if (t < OUTD) {
        float s = V1b[t];
        #pragma unroll 8
        for (int hh = 0; hh < HD; ++hh) s += hid[hh] * V1w[hh * OUTD + t];
        y[t] = s;
    }
    __syncthreads();
    if (t < OUTD) {
        float m = y[0];
        #pragma unroll
        for (int o = 1; o < OUTD; ++o) m = fmaxf(m, y[o]);
        float s = 0.f;
        #pragma unroll
        for (int o = 0; o < OUTD; ++o) s += expf(y[o] - m);
        out[g * OUTD + t] = y[t] - m - logf(s);
    }
}

// ---------------------------------------------------------------------------
extern "C" void kernel_launch(void* const* d_in, const int* in_sizes, int n_in,
                              void* d_out, int out_size) {
    const float* features    = (const float*)d_in[0];
    const float* edge_weight = (const float*)d_in[1];
    const float* W1          = (const float*)d_in[2];
    const float* b1          = (const float*)d_in[3];
    const float* W2          = (const float*)d_in[4];
    const float* b2          = (const float*)d_in[5];
    const float* V0w         = (const float*)d_in[6];
    const float* V0b         = (const float*)d_in[7];
    const float* V1w         = (const float*)d_in[8];
    const float* V1b         = (const float*)d_in[9];
    const int*   edge_index  = (const int*)d_in[10];
    const int*   batch       = (const int*)d_in[11];
    float*       out         = (float*)d_out;

    // CSR build
    k_zero_deg<<<NB, 256>>>();
    k_hist<<<(EE + 255) / 256, 256>>>(edge_index);
    k_blocksum<<<NB, 256>>>();
    k_scan_bsum<<<1, 256>>>();
    k_rowptr_zeropool<<<NB + 256, 256>>>();
    k_scatter<<<(EE + 255) / 256, 256>>>(edge_index, edge_weight);

    // Dense front-end
    k_wc<<<16, 128>>>(W1, b1, W2, b2);
    k_x0<<<(NN + 63) / 64, 256>>>(features);

    // APPNP propagation, atomic-free; final step fuses the pooling.
    float* xa = nullptr; float* xb = nullptr; float* xh = nullptr;
    cudaGetSymbolAddress((void**)&xa, g_xa);
    cudaGetSymbolAddress((void**)&xb, g_xb);
    cudaGetSymbolAddress((void**)&xh, g_h);

    const int prop_grid = (NN * 32 + 255) / 256;   // 6250
    const float* cur = xh;
    for (int k = 0; k < KSTEPS; ++k) {
        int fin = (k == KSTEPS - 1);
        float* nxt = (k % 2 == 0) ? xa : xb;
        k_prop<<<prop_grid, 256>>>(cur, fin ? nullptr : nxt, fin, batch);
        cur = nxt;
    }

    k_head<<<GG, 128>>>(V0w, V0b, V1w, V1b, out);
}

// round 6
// speedup vs baseline: 3.6890x; 1.2704x over previous
#include <cuda_runtime.h>
#include <cuda_fp16.h>

#define NN 50000
#define EE 1600000
#define HD 128
#define H2 64             // HD/2 half2 per row
#define GG 512
#define OUTD 10
#define KSTEPS 10
#define ALPHA 0.1f
#define NB 196            // ceil(NN/256)
// Per-step storage rescale: y_k = x_k / SCALE^k  (SCALE=4, exact power of 2)
#define WS (0.9f / 4.0f)          // folded into edge weights
#define OSCALE 1048576.0f         // 4^10 = 2^20, applied at the final step

// Scratch (device globals; no dynamic allocation allowed)
__device__ float   g_h [NN * HD];    // teleport term h = x0 (fp32)
__device__ __half2 g_x16a[NN * H2];  // ping (scaled fp16 iterate)
__device__ __half2 g_x16b[NN * H2];  // pong
__device__ float   g_Wc[HD * HD];    // fused W1@W2
__device__ float   g_bc[HD];         // fused b1@W2 + b2
__device__ float   g_pooled[GG * HD];

// CSR (dst-sorted) built per launch
__device__ int  g_deg[NN];
__device__ int  g_cursor[NN];
__device__ int  g_rowptr[NN + 1];
__device__ int  g_bsum[NB];
__device__ int  g_boff[NB];
__device__ int2 g_sw[EE];            // packed (src, weight-bits)

// ---------------------------------------------------------------------------
// Fuse the two stacked linears: Wc = W1 @ W2, bc = b1 @ W2 + b2
// ---------------------------------------------------------------------------
__global__ void k_wc(const float* __restrict__ W1, const float* __restrict__ b1,
                     const float* __restrict__ W2, const float* __restrict__ b2) {
    int h = threadIdx.x;
    int d0 = blockIdx.x * 8;
    for (int d = d0; d < d0 + 8; ++d) {
        float s = 0.f;
        #pragma unroll 8
        for (int k = 0; k < HD; ++k) s += W1[d * HD + k] * W2[k * HD + h];
        g_Wc[d * HD + h] = s;
    }
    if (blockIdx.x == 0) {
        float s = b2[h];
        #pragma unroll 8
        for (int k = 0; k < HD; ++k) s += b1[k] * W2[k * HD + h];
        g_bc[h] = s;
    }
}

// ---------------------------------------------------------------------------
// x0 = F^T @ Wc + bc.  Writes fp32 h AND fp16 y0 = x0 (scale 4^0 = 1).
// ---------------------------------------------------------------------------
__global__ __launch_bounds__(256) void k_x0(const float* __restrict__ F) {
    __shared__ float Fs[32][64];
    __shared__ float Ws[32][128];
    int t  = threadIdx.x;
    int nb = blockIdx.x * 64;
    int n0 = (t & 15) * 4;
    int h0 = (t >> 4) * 8;

    float acc[4][8];
    #pragma unroll
    for (int i = 0; i < 4; ++i)
        #pragma unroll
        for (int j = 0; j < 8; ++j) acc[i][j] = 0.f;

    for (int c = 0; c < 4; ++c) {
        __syncthreads();
        for (int i = t; i < 32 * 64; i += 256) {
            int dd = i >> 6, nn = i & 63, n = nb + nn;
            Fs[dd][nn] = (n < NN) ? F[(c * 32 + dd) * NN + n] : 0.f;
        }
        for (int i = t; i < 32 * 128; i += 256) {
            int dd = i >> 7, hh = i & 127;
            Ws[dd][hh] = g_Wc[(c * 32 + dd) * HD + hh];
        }
        __syncthreads();
        #pragma unroll
        for (int d = 0; d < 32; ++d) {
            float4 fa = *(const float4*)&Fs[d][n0];
            float4 w0 = *(const float4*)&Ws[d][h0];
            float4 w1 = *(const float4*)&Ws[d][h0 + 4];
            float f[4] = {fa.x, fa.y, fa.z, fa.w};
            float w[8] = {w0.x, w0.y, w0.z, w0.w, w1.x, w1.y, w1.z, w1.w};
            #pragma unroll
            for (int i = 0; i < 4; ++i)
                #pragma unroll
                for (int j = 0; j < 8; ++j) acc[i][j] += f[i] * w[j];
        }
    }
    #pragma unroll
    for (int i = 0; i < 4; ++i) {
        int n = nb + n0 + i;
        if (n < NN) {
            #pragma unroll
            for (int j = 0; j < 8; j += 4) {
                float4 o = make_float4(acc[i][j]     + g_bc[h0 + j],
                                       acc[i][j + 1] + g_bc[h0 + j + 1],
                                       acc[i][j + 2] + g_bc[h0 + j + 2],
                                       acc[i][j + 3] + g_bc[h0 + j + 3]);
                *(float4*)&g_h[n * HD + h0 + j] = o;
                __half2 p0 = __floats2half2_rn(o.x, o.y);
                __half2 p1 = __floats2half2_rn(o.z, o.w);
                *(uint2*)&g_x16a[n * H2 + (h0 + j) / 2] =
                    make_uint2(*(unsigned*)&p0, *(unsigned*)&p1);
            }
        }
    }
}

// ---------------------------------------------------------------------------
// CSR construction: histogram -> (blocksum, scan, rowptr) -> scatter
// ---------------------------------------------------------------------------
__global__ void k_zero_deg() {
    int i = blockIdx.x * 256 + threadIdx.x;
    if (i < NN) g_deg[i] = 0;
}

__global__ __launch_bounds__(256) void k_hist(const int* __restrict__ ei) {
    int e = blockIdx.x * 256 + threadIdx.x;
    if (e < EE) atomicAdd(&g_deg[ei[EE + e]], 1);
}

__global__ __launch_bounds__(256) void k_blocksum() {
    __shared__ int sm[256];
    int t = threadIdx.x;
    int i = blockIdx.x * 256 + t;
    sm[t] = (i < NN) ? g_deg[i] : 0;
    __syncthreads();
    for (int off = 128; off > 0; off >>= 1) {
        if (t < off) sm[t] += sm[t + off];
        __syncthreads();
    }
    if (t == 0) g_bsum[blockIdx.x] = sm[0];
}

__global__ __launch_bounds__(256) void k_scan_bsum() {
    __shared__ int sm[256];
    int t = threadIdx.x;
    int v = (t < NB) ? g_bsum[t] : 0;
    sm[t] = v;
    __syncthreads();
    for (int off = 1; off < 256; off <<= 1) {
        int u = (t >= off) ? sm[t - off] : 0;
        __syncthreads();
        sm[t] += u;
        __syncthreads();
    }
    if (t < NB) g_boff[t] = sm[t] - v;   // exclusive
}

// blocks [0, NB): rowptr + cursor; blocks [NB, NB+256): zero g_pooled
__global__ __launch_bounds__(256) void k_rowptr_zeropool() {
    int t = threadIdx.x;
    int b = blockIdx.x;
    if (b >= NB) {
        int i = (b - NB) * 256 + t;
        g_pooled[i] = 0.f;
        return;
    }
    __shared__ int sm[256];
    int i = b * 256 + t;
    int v = (i < NN) ? g_deg[i] : 0;
    sm[t] = v;
    __syncthreads();
    for (int off = 1; off < 256; off <<= 1) {
        int u = (t >= off) ? sm[t - off] : 0;
        __syncthreads();
        sm[t] += u;
        __syncthreads();
    }
    int rp = g_boff[b] + sm[t] - v;
    if (i < NN) { g_rowptr[i] = rp; g_cursor[i] = rp; }
    if (b == 0 && t == 0) g_rowptr[NN] = EE;
}

__global__ __launch_bounds__(256) void k_scatter(const int*   __restrict__ ei,
                                                 const float* __restrict__ ew) {
    int e = blockIdx.x * 256 + threadIdx.x;
    if (e >= EE) return;
    int dst = __ldg(&ei[EE + e]);
    int pos = atomicAdd(&g_cursor[dst], 1);
    g_sw[pos] = make_int2(__ldg(&ei[e]), __float_as_int(WS * __ldg(&ew[e])));
}

// ---------------------------------------------------------------------------
// Propagation, atomic-free, scaled-fp16 gather: one warp per dst node,
// lane owns 4 columns (2 half2). fp32 accumulate.
//   y_out[n] = sum_e (0.9/4)*w_e*y_in[src_e] + hscale*h[n]
// final: pooled[batch[n]] += OSCALE * y_out[n]   (recovers x_10 exactly)
// ---------------------------------------------------------------------------
__global__ __launch_bounds__(256) void k_prop(const __half2* __restrict__ xin,
                                              __half2* __restrict__ xout,
                                              float hscale, int final_step,
                                              const int* __restrict__ batch) {
    unsigned warp = (blockIdx.x * 256u + threadIdx.x) >> 5;
    if (warp >= NN) return;
    int lane = threadIdx.x & 31;
    int beg = g_rowptr[warp];
    int end = g_rowptr[warp + 1];

    float4 acc = make_float4(0.f, 0.f, 0.f, 0.f);
    for (int j0 = beg; j0 < end; j0 += 32) {
        int cnt = end - j0;
        if (cnt > 32) cnt = 32;
        int   s = 0;
        float w = 0.f;
        if (lane < cnt) {
            int2 sw = __ldg(&g_sw[j0 + lane]);
            s = sw.x * H2;
            w = __int_as_float(sw.y);
        }
        #pragma unroll 4
        for (int t = 0; t < cnt; ++t) {
            int   ss = __shfl_sync(0xffffffffu, s, t);
            float ww = __shfl_sync(0xffffffffu, w, t);
            uint2 p = __ldg((const uint2*)&xin[ss + lane * 2]);
            float2 v0 = __half22float2(*(__half2*)&p.x);
            float2 v1 = __half22float2(*(__half2*)&p.y);
            acc.x += ww * v0.x;
            acc.y += ww * v0.y;
            acc.z += ww * v1.x;
            acc.w += ww * v1.y;
        }
    }
    float4 hv = *(const float4*)&g_h[warp * HD + lane * 4];
    float4 o = make_float4(acc.x + hscale * hv.x, acc.y + hscale * hv.y,
                           acc.z + hscale * hv.z, acc.w + hscale * hv.w);
    if (final_step) {
        int g = __ldg(&batch[warp]);
        atomicAdd((float4*)&g_pooled[g * HD + lane * 4],
                  make_float4(OSCALE * o.x, OSCALE * o.y,
                              OSCALE * o.z, OSCALE * o.w));
    } else {
        __half2 p0 = __floats2half2_rn(o.x, o.y);
        __half2 p1 = __floats2half2_rn(o.z, o.w);
        *(uint2*)&xout[warp * H2 + lane * 2] =
            make_uint2(*(unsigned*)&p0, *(unsigned*)&p1);
    }
}

// ---------------------------------------------------------------------------
// Head: relu(pooled @ V0w + V0b) @ V1w + V1b -> log_softmax
// ---------------------------------------------------------------------------
__global__ __launch_bounds__(128) void k_head(const float* __restrict__ V0w,
                                              const float* __restrict__ V0b,
                                              const float* __restrict__ V1w,
                                              const float* __restrict__ V1b,
                                              float* __restrict__ out) {
    int g = blockIdx.x, t = threadIdx.x;
    __shared__ float p[HD];
    __shared__ float hid[HD];
    __shared__ float y[OUTD];
    p[t] = g_pooled[g * HD + t];
    __syncthreads();
    float a = V0b[t];
    #pragma unroll 8
    for (int d = 0; d < HD; ++d) a += p[d] * V0w[d * HD + t];
    hid[t] = fmaxf(a, 0.f);
    __syncthreads();
    if (t < OUTD) {
        float s = V1b[t];
        #pragma unroll 8
        for (int hh = 0; hh < HD; ++hh) s += hid[hh] * V1w[hh * OUTD + t];
        y[t] = s;
    }
    __syncthreads();
    if (t < OUTD) {
        float m = y[0];
        #pragma unroll
        for (int o = 1; o < OUTD; ++o) m = fmaxf(m, y[o]);
        float s = 0.f;
        #pragma unroll
        for (int o = 0; o < OUTD; ++o) s += expf(y[o] - m);
        out[g * OUTD + t] = y[t] - m - logf(s);
    }
}

// ---------------------------------------------------------------------------
extern "C" void kernel_launch(void* const* d_in, const int* in_sizes, int n_in,
                              void* d_out, int out_size) {
    const float* features    = (const float*)d_in[0];
    const float* edge_weight = (const float*)d_in[1];
    const float* W1          = (const float*)d_in[2];
    const float* b1          = (const float*)d_in[3];
    const float* W2          = (const float*)d_in[4];
    const float* b2          = (const float*)d_in[5];
    const float* V0w         = (const float*)d_in[6];
    const float* V0b         = (const float*)d_in[7];
    const float* V1w         = (const float*)d_in[8];
    const float* V1b         = (const float*)d_in[9];
    const int*   edge_index  = (const int*)d_in[10];
    const int*   batch       = (const int*)d_in[11];
    float*       out         = (float*)d_out;

    // CSR build
    k_zero_deg<<<NB, 256>>>();
    k_hist<<<(EE + 255) / 256, 256>>>(edge_index);
    k_blocksum<<<NB, 256>>>();
    k_scan_bsum<<<1, 256>>>();
    k_rowptr_zeropool<<<NB + 256, 256>>>();
    k_scatter<<<(EE + 255) / 256, 256>>>(edge_index, edge_weight);

    // Dense front-end
    k_wc<<<16, 128>>>(W1, b1, W2, b2);
    k_x0<<<(NN + 63) / 64, 256>>>(features);

    // APPNP propagation (scaled fp16 iterate); final step fuses the pooling.
    __half2* xa = nullptr; __half2* xb = nullptr;
    cudaGetSymbolAddress((void**)&xa, g_x16a);
    cudaGetSymbolAddress((void**)&xb, g_x16b);

    const int prop_grid = (NN * 32 + 255) / 256;   // 6250
    const __half2* cur = xa;
    float hscale = ALPHA;
    for (int k = 0; k < KSTEPS; ++k) {
        hscale *= 0.25f;                 // ALPHA / 4^(k+1)
        int fin = (k == KSTEPS - 1);
        __half2* nxt = (k % 2 == 0) ? xb : xa;
        k_prop<<<prop_grid, 256>>>(cur, fin ? nullptr : nxt, hscale, fin, batch);
        cur = nxt;
    }

    k_head<<<GG, 128>>>(V0w, V0b, V1w, V1b, out);
}

// round 7
// speedup vs baseline: 3.9310x; 1.0656x over previous
#include <cuda_runtime.h>
#include <cuda_fp16.h>

#define NN 50000
#define EE 1600000
#define HD 128
#define H2 64             // HD/2 half2 per row
#define GG 512
#define OUTD 10
#define KSTEPS 10
#define ALPHA 0.1f
#define NB 196            // ceil(NN/256)
// Per-step storage rescale: y_k = x_k / 4^k  (exact power of 2)
#define WS (0.9f / 4.0f)          // folded into edge weights
#define OSCALE 1048576.0f         // 4^10 = 2^20, applied at the final step

// packed dual-fp32 FMA (sm_103a FFMA2) — bit-exact fp32, 2 MACs/instr
#define FMA_F32X2(acc, a, b) \
    asm("fma.rn.f32x2 %0, %1, %2, %3;" : "=l"(acc) : "l"(a), "l"(b), "l"(acc))
#define PACK_F32X2(out, lo, hi) \
    asm("mov.b64 %0, {%1, %2};" : "=l"(out) : "f"(lo), "f"(hi))
#define UNPACK_F32X2(lo, hi, in) \
    asm("mov.b64 {%0, %1}, %2;" : "=f"(lo), "=f"(hi) : "l"(in))

// Scratch (device globals; no dynamic allocation allowed)
__device__ __half2 g_ah16[NN * H2];  // ALPHA * x0, fp16 (teleport term)
__device__ __half2 g_x16a[NN * H2];  // ping (scaled fp16 iterate)
__device__ __half2 g_x16b[NN * H2];  // pong
__device__ float   g_Wc[HD * HD];    // fused W1@W2
__device__ float   g_bc[HD];         // fused b1@W2 + b2
__device__ float   g_pooled[GG * HD];

// CSR (dst-sorted) built per launch
__device__ int  g_deg[NN];
__device__ int  g_cursor[NN];
__device__ int  g_rowptr[NN + 1];
__device__ int  g_bsum[NB];
__device__ int  g_boff[NB];
__device__ int2 g_sw[EE];            // packed (src, weight-bits)

// ---------------------------------------------------------------------------
// Fuse the two stacked linears: Wc = W1 @ W2, bc = b1 @ W2 + b2
// ---------------------------------------------------------------------------
__global__ void k_wc(const float* __restrict__ W1, const float* __restrict__ b1,
                     const float* __restrict__ W2, const float* __restrict__ b2) {
    int h = threadIdx.x;
    int d0 = blockIdx.x * 8;
    for (int d = d0; d < d0 + 8; ++d) {
        float s = 0.f;
        #pragma unroll 8
        for (int k = 0; k < HD; ++k) s += W1[d * HD + k] * W2[k * HD + h];
        g_Wc[d * HD + h] = s;
    }
    if (blockIdx.x == 0) {
        float s = b2[h];
        #pragma unroll 8
        for (int k = 0; k < HD; ++k) s += b1[k] * W2[k * HD + h];
        g_bc[h] = s;
    }
}

// ---------------------------------------------------------------------------
// x0 = F^T @ Wc + bc.  Writes fp16 y0 = x0 and fp16 ALPHA*x0.
// Inner product uses fma.rn.f32x2 (2 fp32 MACs / instr).
// ---------------------------------------------------------------------------
__global__ __launch_bounds__(256) void k_x0(const float* __restrict__ F) {
    __shared__ float Fs[32][64];
    __shared__ float Ws[32][128];
    int t  = threadIdx.x;
    int nb = blockIdx.x * 64;
    int n0 = (t & 15) * 4;
    int h0 = (t >> 4) * 8;

    unsigned long long accp[4][4];   // [node][col-pair-of-2], packed f32x2
    #pragma unroll
    for (int i = 0; i < 4; ++i)
        #pragma unroll
        for (int j = 0; j < 4; ++j) accp[i][j] = 0ull;

    for (int c = 0; c < 4; ++c) {
        __syncthreads();
        for (int i = t; i < 32 * 64; i += 256) {
            int dd = i >> 6, nn = i & 63, n = nb + nn;
            Fs[dd][nn] = (n < NN) ? F[(c * 32 + dd) * NN + n] : 0.f;
        }
        for (int i = t; i < 32 * 128; i += 256) {
            int dd = i >> 7, hh = i & 127;
            Ws[dd][hh] = g_Wc[(c * 32 + dd) * HD + hh];
        }
        __syncthreads();
        #pragma unroll
        for (int d = 0; d < 32; ++d) {
            float4 fa = *(const float4*)&Fs[d][n0];
            // two consecutive floats reinterpreted as one f32x2 operand
            ulonglong2 wa = *(const ulonglong2*)&Ws[d][h0];      // cols h0..h0+3
            ulonglong2 wb = *(const ulonglong2*)&Ws[d][h0 + 4];  // cols h0+4..h0+7
            unsigned long long wp[4] = {wa.x, wa.y, wb.x, wb.y};
            float f[4] = {fa.x, fa.y, fa.z, fa.w};
            #pragma unroll
            for (int i = 0; i < 4; ++i) {
                unsigned long long fp;
                PACK_F32X2(fp, f[i], f[i]);
                #pragma unroll
                for (int j = 0; j < 4; ++j) FMA_F32X2(accp[i][j], fp, wp[j]);
            }
        }
    }
    #pragma unroll
    for (int i = 0; i < 4; ++i) {
        int n = nb + n0 + i;
        if (n < NN) {
            float o[8];
            #pragma unroll
            for (int j = 0; j < 4; ++j) {
                float lo, hi;
                UNPACK_F32X2(lo, hi, accp[i][j]);
                o[2 * j]     = lo + g_bc[h0 + 2 * j];
                o[2 * j + 1] = hi + g_bc[h0 + 2 * j + 1];
            }
            #pragma unroll
            for (int j = 0; j < 8; j += 4) {
                __half2 p0 = __floats2half2_rn(o[j],     o[j + 1]);
                __half2 p1 = __floats2half2_rn(o[j + 2], o[j + 3]);
                *(uint2*)&g_x16a[n * H2 + (h0 + j) / 2] =
                    make_uint2(*(unsigned*)&p0, *(unsigned*)&p1);
                __half2 a0 = __floats2half2_rn(ALPHA * o[j],     ALPHA * o[j + 1]);
                __half2 a1 = __floats2half2_rn(ALPHA * o[j + 2], ALPHA * o[j + 3]);
                *(uint2*)&g_ah16[n * H2 + (h0 + j) / 2] =
                    make_uint2(*(unsigned*)&a0, *(unsigned*)&a1);
            }
        }
    }
}

// ---------------------------------------------------------------------------
// CSR construction: histogram -> (blocksum, scan, rowptr) -> scatter
// ---------------------------------------------------------------------------
__global__ void k_zero_deg() {
    int i = blockIdx.x * 256 + threadIdx.x;
    if (i < NN) g_deg[i] = 0;
}

__global__ __launch_bounds__(256) void k_hist(const int* __restrict__ ei) {
    int e = blockIdx.x * 256 + threadIdx.x;
    if (e < EE) atomicAdd(&g_deg[ei[EE + e]], 1);
}

__global__ __launch_bounds__(256) void k_blocksum() {
    __shared__ int sm[256];
    int t = threadIdx.x;
    int i = blockIdx.x * 256 + t;
    sm[t] = (i < NN) ? g_deg[i] : 0;
    __syncthreads();
    for (int off = 128; off > 0; off >>= 1) {
        if (t < off) sm[t] += sm[t + off];
        __syncthreads();
    }
    if (t == 0) g_bsum[blockIdx.x] = sm[0];
}

__global__ __launch_bounds__(256) void k_scan_bsum() {
    __shared__ int sm[256];
    int t = threadIdx.x;
    int v = (t < NB) ? g_bsum[t] : 0;
    sm[t] = v;
    __syncthreads();
    for (int off = 1; off < 256; off <<= 1) {
        int u = (t >= off) ? sm[t - off] : 0;
        __syncthreads();
        sm[t] += u;
        __syncthreads();
    }
    if (t < NB) g_boff[t] = sm[t] - v;   // exclusive
}

// blocks [0, NB): rowptr + cursor; blocks [NB, NB+256): zero g_pooled
__global__ __launch_bounds__(256) void k_rowptr_zeropool() {
    int t = threadIdx.x;
    int b = blockIdx.x;
    if (b >= NB) {
        int i = (b - NB) * 256 + t;
        g_pooled[i] = 0.f;
        return;
    }
    __shared__ int sm[256];
    int i = b * 256 + t;
    int v = (i < NN) ? g_deg[i] : 0;
    sm[t] = v;
    __syncthreads();
    for (int off = 1; off < 256; off <<= 1) {
        int u = (t >= off) ? sm[t - off] : 0;
        __syncthreads();
        sm[t] += u;
        __syncthreads();
    }
    int rp = g_boff[b] + sm[t] - v;
    if (i < NN) { g_rowptr[i] = rp; g_cursor[i] = rp; }
    if (b == 0 && t == 0) g_rowptr[NN] = EE;
}

__global__ __launch_bounds__(256) void k_scatter(const int*   __restrict__ ei,
                                                 const float* __restrict__ ew) {
    int e = blockIdx.x * 256 + threadIdx.x;
    if (e >= EE) return;
    int dst = __ldg(&ei[EE + e]);
    int pos = atomicAdd(&g_cursor[dst], 1);
    g_sw[pos] = make_int2(__ldg(&ei[e]), __float_as_int(WS * __ldg(&ew[e])));
}

// ---------------------------------------------------------------------------
// Propagation, atomic-free, scaled-fp16 gather: one warp per dst node,
// lane owns 4 columns (2 half2). fp32 accumulate. Uniform LDG broadcast of
// the edge record (no shfl).
//   y_out[n] = sum_e (0.9/4)*w_e*y_in[src_e] + hs*(ALPHA*x0)[n]
// final: pooled[batch[n]] += OSCALE * y_out[n]
// ---------------------------------------------------------------------------
__global__ __launch_bounds__(256) void k_prop(const __half2* __restrict__ xin,
                                              __half2* __restrict__ xout,
                                              float hs, int final_step,
                                              const int* __restrict__ batch) {
    unsigned warp = (blockIdx.x * 256u + threadIdx.x) >> 5;
    if (warp >= NN) return;
    int lane = threadIdx.x & 31;
    int beg = g_rowptr[warp];
    int end = g_rowptr[warp + 1];

    float4 acc = make_float4(0.f, 0.f, 0.f, 0.f);
    #pragma unroll 4
    for (int j = beg; j < end; ++j) {
        int2 sw = __ldg(&g_sw[j]);                 // uniform across warp
        float w = __int_as_float(sw.y);
        uint2 p = __ldg((const uint2*)&xin[sw.x * H2 + lane * 2]);
        float2 v0 = __half22float2(*(__half2*)&p.x);
        float2 v1 = __half22float2(*(__half2*)&p.y);
        acc.x += w * v0.x;
        acc.y += w * v0.y;
        acc.z += w * v1.x;
        acc.w += w * v1.y;
    }
    uint2 hp = *(const uint2*)&g_ah16[warp * H2 + lane * 2];
    float2 h0 = __half22float2(*(__half2*)&hp.x);
    float2 h1 = __half22float2(*(__half2*)&hp.y);
    float4 o = make_float4(acc.x + hs * h0.x, acc.y + hs * h0.y,
                           acc.z + hs * h1.x, acc.w + hs * h1.y);
    if (final_step) {
        int g = __ldg(&batch[warp]);
        atomicAdd((float4*)&g_pooled[g * HD + lane * 4],
                  make_float4(OSCALE * o.x, OSCALE * o.y,
                              OSCALE * o.z, OSCALE * o.w));
    } else {
        __half2 p0 = __floats2half2_rn(o.x, o.y);
        __half2 p1 = __floats2half2_rn(o.z, o.w);
        *(uint2*)&xout[warp * H2 + lane * 2] =
            make_uint2(*(unsigned*)&p0, *(unsigned*)&p1);
    }
}

// ---------------------------------------------------------------------------
// Head: relu(pooled @ V0w + V0b) @ V1w + V1b -> log_softmax
// ---------------------------------------------------------------------------
__global__ __launch_bounds__(128) void k_head(const float* __restrict__ V0w,
                                              const float* __restrict__ V0b,
                                              const float* __restrict__ V1w,
                                              const float* __restrict__ V1b,
                                              float* __restrict__ out) {
    int g = blockIdx.x, t = threadIdx.x;
    __shared__ float p[HD];
    __shared__ float hid[HD];
    __shared__ float y[OUTD];
    p[t] = g_pooled[g * HD + t];
    __syncthreads();
    float a = V0b[t];
    #pragma unroll 8
    for (int d = 0; d < HD; ++d) a += p[d] * V0w[d * HD + t];
    hid[t] = fmaxf(a, 0.f);
    __syncthreads();
    if (t < OUTD) {
        float s = V1b[t];
        #pragma unroll 8
        for (int hh = 0; hh < HD; ++hh) s += hid[hh] * V1w[hh * OUTD + t];
        y[t] = s;
    }
    __syncthreads();
    if (t < OUTD) {
        float m = y[0];
        #pragma unroll
        for (int o = 1; o < OUTD; ++o) m = fmaxf(m, y[o]);
        float s = 0.f;
        #pragma unroll
        for (int o = 0; o < OUTD; ++o) s += expf(y[o] - m);
        out[g * OUTD + t] = y[t] - m - logf(s);
    }
}

// ---------------------------------------------------------------------------
extern "C" void kernel_launch(void* const* d_in, const int* in_sizes, int n_in,
                              void* d_out, int out_size) {
    const float* features    = (const float*)d_in[0];
    const float* edge_weight = (const float*)d_in[1];
    const float* W1          = (const float*)d_in[2];
    const float* b1          = (const float*)d_in[3];
    const float* W2          = (const float*)d_in[4];
    const float* b2          = (const float*)d_in[5];
    const float* V0w         = (const float*)d_in[6];
    const float* V0b         = (const float*)d_in[7];
    const float* V1w         = (const float*)d_in[8];
    const float* V1b         = (const float*)d_in[9];
    const int*   edge_index  = (const int*)d_in[10];
    const int*   batch       = (const int*)d_in[11];
    float*       out         = (float*)d_out;

    // CSR build
    k_zero_deg<<<NB, 256>>>();
    k_hist<<<(EE + 255) / 256, 256>>>(edge_index);
    k_blocksum<<<NB, 256>>>();
    k_scan_bsum<<<1, 256>>>();
    k_rowptr_zeropool<<<NB + 256, 256>>>();
    k_scatter<<<(EE + 255) / 256, 256>>>(edge_index, edge_weight);

    // Dense front-end
    k_wc<<<16, 128>>>(W1, b1, W2, b2);
    k_x0<<<(NN + 63) / 64, 256>>>(features);

    // APPNP propagation (scaled fp16 iterate); final step fuses the pooling.
    __half2* xa = nullptr; __half2* xb = nullptr;
    cudaGetSymbolAddress((void**)&xa, g_x16a);
    cudaGetSymbolAddress((void**)&xb, g_x16b);

    const int prop_grid = (NN * 32 + 255) / 256;   // 6250
    const __half2* cur = xa;
    float hs = 1.0f;
    for (int k = 0; k < KSTEPS; ++k) {
        hs *= 0.25f;                     // 4^-(k+1); ALPHA folded into g_ah16
        int fin = (k == KSTEPS - 1);
        __half2* nxt = (k % 2 == 0) ? xb : xa;
        k_prop<<<prop_grid, 256>>>(cur, fin ? nullptr : nxt, hs, fin, batch);
        cur = nxt;
    }

    k_head<<<GG, 128>>>(V0w, V0b, V1w, V1b, out);
}